// round 4
// baseline (speedup 1.0000x reference)
#include <cuda_runtime.h>
#include <stdint.h>

// RecyclingEmbedder: out[i,j,:] = W[:,bin(d_ij)] + b  (b only if no bin hit)
//
// R3 ncu: DRAM 73.9% (top), L1 61.8%, issue 17%. Store bursts are gated by a
// dependent SHFL (26-cyc, MIO) per row. R4: replace 32 shuffles/group with 2
// ballots (m15 = "no bin", ~83%; m0 = bin 0, ~15%); inner loop is then
// bit-test + select + STG with no MIO dependency. Rare rows (bins 1-14, ~2%)
// keep a warp-uniform shfl + LDS fallback.

#define N_PTS   1536
#define D_PAIR  128
#define GROUPS_PER_ROW (N_PTS / 32)          // 48
#define NGROUPS (N_PTS * GROUPS_PER_ROW)     // 73728
#define NWARPS_PER_BLOCK 8
#define BLOCK_THREADS (NWARPS_PER_BLOCK * 32)

__global__ __launch_bounds__(BLOCK_THREADS)
void recycling_embedder_kernel(const float* __restrict__ x,
                               const float* __restrict__ W,
                               const float* __restrict__ b,
                               float* __restrict__ out)
{
    __shared__ float s_table[16 * D_PAIR];   // 8 KB:  row k = W[:,k]+b, row 15 = b
    __shared__ float s_x[N_PTS * 3];         // 18 KB

    const int tid = threadIdx.x;

    // table[k][p] = W[p*15+k] + b[p] for k<15; table[15][p] = b[p].
    for (int idx = tid; idx < 16 * D_PAIR; idx += BLOCK_THREADS) {
        int k = idx >> 7;
        int p = idx & (D_PAIR - 1);
        float v = b[p];
        if (k < 15) v += W[p * 15 + k];
        s_table[idx] = v;
    }
    for (int idx = tid; idx < N_PTS * 3; idx += BLOCK_THREADS) {
        s_x[idx] = x[idx];
    }
    __syncthreads();

    const int lane = tid & 31;
    const int warp = tid >> 5;
    const int gwarp  = blockIdx.x * NWARPS_PER_BLOCK + warp;
    const int nwarps = gridDim.x * NWARPS_PER_BLOCK;

    // Hot rows in registers: row 15 (b only, ~83%) and row 0 (~15%).
    const float4 v15 = *reinterpret_cast<const float4*>(&s_table[15 * D_PAIR + lane * 4]);
    const float4 v0  = *reinterpret_cast<const float4*>(&s_table[ 0 * D_PAIR + lane * 4]);

    for (int g = gwarp; g < NGROUPS; g += nwarps) {
        const int i  = g / GROUPS_PER_ROW;
        const int j0 = (g - i * GROUPS_PER_ROW) * 32;
        const int j  = j0 + lane;

        // Phase 1: one pair per lane. Match reference rounding exactly:
        // no FMA contraction, sum order (dx^2 + dy^2) + dz^2.
        float dx = s_x[i * 3 + 0] - s_x[j * 3 + 0];
        float dy = s_x[i * 3 + 1] - s_x[j * 3 + 1];
        float dz = s_x[i * 3 + 2] - s_x[j * 3 + 2];
        float d  = __fadd_rn(__fadd_rn(__fmul_rn(dx, dx), __fmul_rn(dy, dy)),
                             __fmul_rn(dz, dz));

        int bi = 15;  // default: no bin hit -> b-only row
        #pragma unroll
        for (int k = 0; k < 15; k++) {
            const float e0 = 3.25f + 1.25f * (float)k;
            const float lo = e0 * e0;                       // folded at compile time
            const float e1 = 3.25f + 1.25f * (float)(k + 1);
            const float hi = (k == 14) ? 100000000.0f : e1 * e1;
            if (d > lo && d < hi) bi = k;
        }

        // Classify all 32 rows with two ballots (warp-uniform masks).
        const unsigned m15 = __ballot_sync(0xffffffffu, bi == 15);
        const unsigned m0  = __ballot_sync(0xffffffffu, bi == 0);

        // Phase 2: stream 32 rows (16 KB contiguous). No per-row MIO dependency
        // on the hot path; rare rows (~2%) take a warp-uniform shfl + LDS.
        float4* dst = reinterpret_cast<float4*>(
                          out + ((size_t)i * N_PTS + j0) * D_PAIR) + lane;
        #pragma unroll
        for (int p = 0; p < 32; p++) {
            float4 v;
            if ((m15 >> p) & 1u) {
                v = v15;
            } else if ((m0 >> p) & 1u) {
                v = v0;
            } else {
                int bp = __shfl_sync(0xffffffffu, bi, p);   // uniform branch: safe
                v = *reinterpret_cast<const float4*>(
                        &s_table[bp * D_PAIR + lane * 4]);
            }
            __stcs(&dst[p * (D_PAIR / 4)], v);   // STG.E.128 streaming
        }
    }
}

extern "C" void kernel_launch(void* const* d_in, const int* in_sizes, int n_in,
                              void* d_out, int out_size)
{
    const float* x = (const float*)d_in[0];   // [1536, 3]
    const float* W = (const float*)d_in[1];   // [128, 15]
    const float* b = (const float*)d_in[2];   // [128]
    float* out = (float*)d_out;               // [1536, 1536, 128]

    // 1184 = 148 SMs * 8 blocks: one full wave, SM-balanced.
    recycling_embedder_kernel<<<1184, BLOCK_THREADS>>>(x, W, b, out);
}